// round 1
// baseline (speedup 1.0000x reference)
#include <cuda_runtime.h>

static constexpr int NMAX = 8192;

// Scratch (device globals — no allocation allowed)
__device__ float g_dinv[NMAX];
__device__ float g_S[256];           // 4 x C_in  reduction vectors
__device__ float g_T[256];           // 4 x C_out projected vectors
__device__ float g_xw[NMAX * 32];    // per-node transformed features (pre-aggregation)
__device__ float g_agg[NMAX * 32];   // aggregation accumulator / layer output

__global__ void k_deg_init(int n) {
    int i = blockIdx.x * blockDim.x + threadIdx.x;
    if (i < n) g_dinv[i] = 1.0f;  // self-loop contributes 1 to degree
}

__global__ void k_deg_count(const int* __restrict__ ei, int E) {
    int e = blockIdx.x * blockDim.x + threadIdx.x;
    if (e < E) atomicAdd(&g_dinv[ei[E + e]], 1.0f);  // dst row
}

__global__ void k_deg_rsqrt(int n) {
    int i = blockIdx.x * blockDim.x + threadIdx.x;
    if (i < n) g_dinv[i] = rsqrtf(g_dinv[i]);  // deg >= 1 always (self-loops)
}

// S0 = sum h ; S1 = sum r*h ; S2x = sum px*h ; S2y = sum py*h   (per channel)
__global__ void k_reduce_S(const float* __restrict__ h, const float* __restrict__ pos,
                           int n, int C, int do_relu) {
    int c    = threadIdx.x % C;
    int lane = threadIdx.x / C;
    int rpb  = blockDim.x / C;
    float s0 = 0.f, s1 = 0.f, s2x = 0.f, s2y = 0.f;
    for (int i = blockIdx.x * rpb + lane; i < n; i += gridDim.x * rpb) {
        float v = h[i * C + c];
        if (do_relu) v = fmaxf(v, 0.0f);
        float px = pos[2 * i], py = pos[2 * i + 1];
        float r = px * px + py * py;
        s0 += v; s1 += r * v; s2x += px * v; s2y += py * v;
    }
    atomicAdd(&g_S[c], s0);
    atomicAdd(&g_S[C + c], s1);
    atomicAdd(&g_S[2 * C + c], s2x);
    atomicAdd(&g_S[3 * C + c], s2y);
}

// T[row] = S[row] @ W   (4 tiny GEMVs; launched with exactly 4*Cout threads)
__global__ void k_project_T(const float* __restrict__ W, int Cin, int Cout) {
    int t = threadIdx.x;
    int row = t / Cout, c = t % Cout;
    float acc = 0.f;
    for (int k = 0; k < Cin; k++) acc += g_S[row * Cin + k] * W[k * Cout + c];
    g_T[row * Cout + c] = acc;
}

// xw[i,c] = (1 - cc*r_i)*T0[c] - cc*T1[c] + 2cc*(px*T2x[c] + py*T2y[c])
// agg[i,c] = xw[i,c] * dinv[i]^2 + bias[c]   (self-loop message + bias)
__global__ void k_expand(const float* __restrict__ pos, const float* __restrict__ bias,
                         int n, int C) {
    int t = blockIdx.x * blockDim.x + threadIdx.x;
    int groups = C >> 2;
    int i = t / groups;
    if (i >= n) return;
    int g = t - i * groups;
    float px = pos[2 * i], py = pos[2 * i + 1];
    float r = px * px + py * py;
    const float cc = 5.0e-7f;  // 1/(2*1000^2)
    float di = g_dinv[i], sl = di * di;
    int cb = 4 * g;
    float4 xv, av;
    float* xp = &xv.x;
    float* ap = &av.x;
#pragma unroll
    for (int k = 0; k < 4; k++) {
        int c = cb + k;
        float t0 = g_T[c], t1 = g_T[C + c], t2x = g_T[2 * C + c], t2y = g_T[3 * C + c];
        float v = t0 - cc * (r * t0 + t1) + 2.0f * cc * (px * t2x + py * t2y);
        xp[k] = v;
        ap[k] = v * sl + bias[c];
    }
    *reinterpret_cast<float4*>(&g_xw[i * C + cb]) = xv;
    *reinterpret_cast<float4*>(&g_agg[i * C + cb]) = av;
}

// Scatter-aggregate edge messages with vector L2 reductions.
template <int C>
__global__ void k_edge(const int* __restrict__ ei, int E) {
    int e = blockIdx.x * blockDim.x + threadIdx.x;
    if (e >= E) return;
    int s = ei[e], d = ei[E + e];
    float nrm = g_dinv[s] * g_dinv[d];
    const float4* row = reinterpret_cast<const float4*>(&g_xw[s * C]);
    float* out = &g_agg[d * C];
#pragma unroll
    for (int g = 0; g < C / 4; g++) {
        float4 v = row[g];
        asm volatile("red.global.add.v4.f32 [%0], {%1,%2,%3,%4};"
                     :: "l"(out + 4 * g),
                        "f"(v.x * nrm), "f"(v.y * nrm), "f"(v.z * nrm), "f"(v.w * nrm)
                     : "memory");
    }
}

__global__ void k_logsoftmax16(float* __restrict__ out, int n) {
    int i = blockIdx.x * blockDim.x + threadIdx.x;
    if (i >= n) return;
    float v[16];
    const float4* row = reinterpret_cast<const float4*>(&g_agg[i * 16]);
#pragma unroll
    for (int q = 0; q < 4; q++) {
        float4 t = row[q];
        v[4 * q] = t.x; v[4 * q + 1] = t.y; v[4 * q + 2] = t.z; v[4 * q + 3] = t.w;
    }
    float m = v[0];
#pragma unroll
    for (int k = 1; k < 16; k++) m = fmaxf(m, v[k]);
    float s = 0.f;
#pragma unroll
    for (int k = 0; k < 16; k++) s += expf(v[k] - m);
    float l = m + logf(s);
    float4* o = reinterpret_cast<float4*>(out + i * 16);
#pragma unroll
    for (int q = 0; q < 4; q++) {
        float4 t;
        t.x = v[4 * q] - l; t.y = v[4 * q + 1] - l;
        t.z = v[4 * q + 2] - l; t.w = v[4 * q + 3] - l;
        o[q] = t;
    }
}

extern "C" void kernel_launch(void* const* d_in, const int* in_sizes, int n_in,
                              void* d_out, int out_size) {
    const float* x   = (const float*)d_in[0];
    const float* pos = (const float*)d_in[1];
    const int*   ei  = (const int*)d_in[2];
    const float* W1  = (const float*)d_in[3];
    const float* b1  = (const float*)d_in[4];
    const float* W2  = (const float*)d_in[5];
    const float* b2  = (const float*)d_in[6];
    const float* W3  = (const float*)d_in[7];
    const float* b3  = (const float*)d_in[8];
    int n = in_sizes[1] / 2;   // pos is (N,2)
    int E = in_sizes[2] / 2;   // edge_index is (2,E)

    float* pS   = nullptr;
    float* pagg = nullptr;
    cudaGetSymbolAddress((void**)&pS, g_S);
    cudaGetSymbolAddress((void**)&pagg, g_agg);

    int nb = (n + 255) / 256;
    int eb = (E + 255) / 256;

    // Degrees / symmetric normalization
    k_deg_init<<<nb, 256>>>(n);
    k_deg_count<<<eb, 256>>>(ei, E);
    k_deg_rsqrt<<<nb, 256>>>(n);

    // Layer 1: input x (C=64) -> hidden 32
    cudaMemsetAsync(pS, 0, 256 * sizeof(float), 0);
    k_reduce_S<<<64, 256>>>(x, pos, n, 64, 0);
    k_project_T<<<1, 4 * 32>>>(W1, 64, 32);
    k_expand<<<(n * 8 + 255) / 256, 256>>>(pos, b1, n, 32);
    k_edge<32><<<eb, 256>>>(ei, E);

    // Layer 2: relu(agg) (C=32) -> hidden 32
    cudaMemsetAsync(pS, 0, 256 * sizeof(float), 0);
    k_reduce_S<<<64, 256>>>(pagg, pos, n, 32, 1);
    k_project_T<<<1, 4 * 32>>>(W2, 32, 32);
    k_expand<<<(n * 8 + 255) / 256, 256>>>(pos, b2, n, 32);
    k_edge<32><<<eb, 256>>>(ei, E);

    // Layer 3: relu(agg) (C=32) -> out 16
    cudaMemsetAsync(pS, 0, 256 * sizeof(float), 0);
    k_reduce_S<<<64, 256>>>(pagg, pos, n, 32, 1);
    k_project_T<<<1, 4 * 16>>>(W3, 32, 16);
    k_expand<<<(n * 4 + 255) / 256, 256>>>(pos, b3, n, 16);
    k_edge<16><<<eb, 256>>>(ei, E);

    k_logsoftmax16<<<nb, 256>>>((float*)d_out, n);
}

// round 2
// speedup vs baseline: 2.8331x; 2.8331x over previous
#include <cuda_runtime.h>

static constexpr int NMAX = 8192;
static constexpr float CC = 5.0e-7f;   // 1/(2*1000^2)

// Scratch (device globals — no allocation allowed)
__device__ float  g_deg[NMAX];
__device__ float4 g_geom[NMAX];              // {px, py, r, dinv}
__device__ float4 g_U[NMAX];                 // {u0, u1(=Σdi*r), ux, uy}
__device__ __align__(16) float g_S[768];     // 3 layer S buffers (4*C each)
__device__ __align__(16) float g_T[256];     // 4 x C_out projected vectors

__device__ __forceinline__ void redv4(float* p, float a, float b, float c, float d) {
    asm volatile("red.global.add.v4.f32 [%0], {%1,%2,%3,%4};"
                 :: "l"(p), "f"(a), "f"(b), "f"(c), "f"(d) : "memory");
}

__global__ void k_init(int n) {
    int i = blockIdx.x * blockDim.x + threadIdx.x;
    if (i < n) { g_deg[i] = 1.0f; g_U[i] = make_float4(0.f, 0.f, 0.f, 0.f); }
    if (i < 768) g_S[i] = 0.0f;
}

__global__ void k_deg_count(const int* __restrict__ ei, int E) {
    int e = blockIdx.x * blockDim.x + threadIdx.x;
    if (e < E) atomicAdd(&g_deg[ei[E + e]], 1.0f);
}

__global__ void k_geom(const float* __restrict__ pos, int n) {
    int i = blockIdx.x * blockDim.x + threadIdx.x;
    if (i >= n) return;
    float px = pos[2 * i], py = pos[2 * i + 1];
    g_geom[i] = make_float4(px, py, px * px + py * py, rsqrtf(g_deg[i]));
}

// One-time edge pass: U[d] += dinv[s] * {1, r_s, px_s, py_s}
__global__ void k_U(const int* __restrict__ ei, int E) {
    int e = blockIdx.x * blockDim.x + threadIdx.x;
    if (e >= E) return;
    int s = ei[e], d = ei[E + e];
    float4 g = g_geom[s];
    float di = g.w;
    redv4(reinterpret_cast<float*>(&g_U[d]), di, di * g.z, di * g.x, di * g.y);
}

// S sums over raw input x (C=64, no relu): S[q*C + c]
template <int C>
__global__ void k_reduce_S(const float* __restrict__ h, float* __restrict__ Sout, int n) {
    constexpr int G = C / 4;               // float4 groups per row
    constexpr int RPB = 256 / G;           // rows per block per iter
    __shared__ float4 sm[256 * 4];
    int t = threadIdx.x;
    int g = t % G, rl = t / G;
    float4 s0 = {0,0,0,0}, s1 = {0,0,0,0}, s2 = {0,0,0,0}, s3 = {0,0,0,0};
    for (int i0 = blockIdx.x * RPB; i0 < n; i0 += gridDim.x * RPB) {
        int i = i0 + rl;
        float4 v = *reinterpret_cast<const float4*>(&h[i * C + 4 * g]);
        float4 ge = g_geom[i];
        s0.x += v.x; s0.y += v.y; s0.z += v.z; s0.w += v.w;
        s1.x += ge.z * v.x; s1.y += ge.z * v.y; s1.z += ge.z * v.z; s1.w += ge.z * v.w;
        s2.x += ge.x * v.x; s2.y += ge.x * v.y; s2.z += ge.x * v.z; s2.w += ge.x * v.w;
        s3.x += ge.y * v.x; s3.y += ge.y * v.y; s3.z += ge.y * v.z; s3.w += ge.y * v.w;
    }
    sm[t * 4 + 0] = s0; sm[t * 4 + 1] = s1; sm[t * 4 + 2] = s2; sm[t * 4 + 3] = s3;
    __syncthreads();
    for (int s = RPB / 2; s >= 1; s >>= 1) {
        if (rl < s) {
            int o = (t + s * G) * 4;
#pragma unroll
            for (int q = 0; q < 4; q++) {
                float4 a = sm[t * 4 + q], b = sm[o + q];
                a.x += b.x; a.y += b.y; a.z += b.z; a.w += b.w;
                sm[t * 4 + q] = a;
            }
        }
        __syncthreads();
    }
    if (rl == 0) {
#pragma unroll
        for (int q = 0; q < 4; q++) {
            float4 v = sm[t * 4 + q];
            redv4(&Sout[q * C + 4 * g], v.x, v.y, v.z, v.w);
        }
    }
}

// T[q*Cout + c] = sum_k S[q*Cin + k] * W[k*Cout + c]   (launch with 4*Cout threads)
__global__ void k_project(const float* __restrict__ S, const float* __restrict__ W,
                          int Cin, int Cout) {
    int t = threadIdx.x;
    int row = t / Cout, c = t % Cout;
    float acc = 0.f;
    for (int k = 0; k < Cin; k++) acc += S[row * Cin + k] * W[k * Cout + c];
    g_T[row * Cout + c] = acc;
}

// Per-node coefficients a0..a3 combining edge-aggregate (U) and self-loop terms.
__device__ __forceinline__ float4 node_coeffs(float4 ge, float4 u) {
    float px = ge.x, py = ge.y, r = ge.z, di = ge.w;
    float di2 = di * di;
    float4 a;
    a.x = di * (u.x - CC * u.y) + di2 * (1.0f - CC * r);   // * T0
    a.y = -CC * (di * u.x + di2);                          // * T1
    a.z = 2.0f * CC * (di * u.z + di2 * px);               // * T2x
    a.w = 2.0f * CC * (di * u.w + di2 * py);               // * T2y
    return a;
}

// Fused: compute h = relu(layer output) for C=32, and accumulate next layer's S sums.
__global__ void k_combine_reduce32(const float* __restrict__ bias,
                                   float* __restrict__ Sout, int n) {
    constexpr int C = 32, G = 8, RPB = 32;
    __shared__ float4 sm[256 * 4];
    int t = threadIdx.x;
    int g = t % G, rl = t / G;
    float4 s0 = {0,0,0,0}, s1 = {0,0,0,0}, s2 = {0,0,0,0}, s3 = {0,0,0,0};
    float4 t0 = *reinterpret_cast<const float4*>(&g_T[4 * g]);
    float4 t1 = *reinterpret_cast<const float4*>(&g_T[C + 4 * g]);
    float4 t2 = *reinterpret_cast<const float4*>(&g_T[2 * C + 4 * g]);
    float4 t3 = *reinterpret_cast<const float4*>(&g_T[3 * C + 4 * g]);
    float4 bv = *reinterpret_cast<const float4*>(&bias[4 * g]);
    for (int i0 = blockIdx.x * RPB; i0 < n; i0 += gridDim.x * RPB) {
        int i = i0 + rl;
        float4 ge = g_geom[i];
        float4 a = node_coeffs(ge, g_U[i]);
        float4 v;
        v.x = fmaxf(a.x * t0.x + a.y * t1.x + a.z * t2.x + a.w * t3.x + bv.x, 0.f);
        v.y = fmaxf(a.x * t0.y + a.y * t1.y + a.z * t2.y + a.w * t3.y + bv.y, 0.f);
        v.z = fmaxf(a.x * t0.z + a.y * t1.z + a.z * t2.z + a.w * t3.z + bv.z, 0.f);
        v.w = fmaxf(a.x * t0.w + a.y * t1.w + a.z * t2.w + a.w * t3.w + bv.w, 0.f);
        s0.x += v.x; s0.y += v.y; s0.z += v.z; s0.w += v.w;
        s1.x += ge.z * v.x; s1.y += ge.z * v.y; s1.z += ge.z * v.z; s1.w += ge.z * v.w;
        s2.x += ge.x * v.x; s2.y += ge.x * v.y; s2.z += ge.x * v.z; s2.w += ge.x * v.w;
        s3.x += ge.y * v.x; s3.y += ge.y * v.y; s3.z += ge.y * v.z; s3.w += ge.y * v.w;
    }
    sm[t * 4 + 0] = s0; sm[t * 4 + 1] = s1; sm[t * 4 + 2] = s2; sm[t * 4 + 3] = s3;
    __syncthreads();
    for (int s = RPB / 2; s >= 1; s >>= 1) {
        if (rl < s) {
            int o = (t + s * G) * 4;
#pragma unroll
            for (int q = 0; q < 4; q++) {
                float4 a = sm[t * 4 + q], b = sm[o + q];
                a.x += b.x; a.y += b.y; a.z += b.z; a.w += b.w;
                sm[t * 4 + q] = a;
            }
        }
        __syncthreads();
    }
    if (rl == 0) {
#pragma unroll
        for (int q = 0; q < 4; q++) {
            float4 v = sm[t * 4 + q];
            redv4(&Sout[q * C + 4 * g], v.x, v.y, v.z, v.w);
        }
    }
}

// Final layer (C=16, no relu) fused with log_softmax.
__global__ void k_final16(const float* __restrict__ bias, float* __restrict__ out, int n) {
    int i = blockIdx.x * blockDim.x + threadIdx.x;
    if (i >= n) return;
    float4 a = node_coeffs(g_geom[i], g_U[i]);
    float v[16];
#pragma unroll
    for (int c = 0; c < 16; c++)
        v[c] = a.x * g_T[c] + a.y * g_T[16 + c] + a.z * g_T[32 + c] + a.w * g_T[48 + c]
             + bias[c];
    float m = v[0];
#pragma unroll
    for (int c = 1; c < 16; c++) m = fmaxf(m, v[c]);
    float s = 0.f;
#pragma unroll
    for (int c = 0; c < 16; c++) s += __expf(v[c] - m);
    float l = m + __logf(s);
    float4* o = reinterpret_cast<float4*>(out + i * 16);
#pragma unroll
    for (int q = 0; q < 4; q++) {
        float4 w;
        w.x = v[4 * q] - l;     w.y = v[4 * q + 1] - l;
        w.z = v[4 * q + 2] - l; w.w = v[4 * q + 3] - l;
        o[q] = w;
    }
}

extern "C" void kernel_launch(void* const* d_in, const int* in_sizes, int n_in,
                              void* d_out, int out_size) {
    const float* x   = (const float*)d_in[0];
    const float* pos = (const float*)d_in[1];
    const int*   ei  = (const int*)d_in[2];
    const float* W1  = (const float*)d_in[3];
    const float* b1  = (const float*)d_in[4];
    const float* W2  = (const float*)d_in[5];
    const float* b2  = (const float*)d_in[6];
    const float* W3  = (const float*)d_in[7];
    const float* b3  = (const float*)d_in[8];
    int n = in_sizes[1] / 2;   // pos is (N,2)
    int E = in_sizes[2] / 2;   // edge_index is (2,E)

    float* pS = nullptr;
    cudaGetSymbolAddress((void**)&pS, g_S);
    float* S1 = pS;            // layer1: 4*64
    float* S2 = pS + 256;      // layer2: 4*32
    float* S3 = pS + 384;      // layer3: 4*32

    int nb = (n + 255) / 256;
    int eb = (E + 255) / 256;

    // Graph-dependent, layer-independent precompute
    k_init<<<nb, 256>>>(n);
    k_deg_count<<<eb, 256>>>(ei, E);
    k_geom<<<nb, 256>>>(pos, n);
    k_U<<<eb, 256>>>(ei, E);

    // Layer 1 reduction over x (C=64)
    k_reduce_S<64><<<128, 256>>>(x, S1, n);
    k_project<<<1, 128>>>(S1, W1, 64, 32);

    // Layer 1 output -> layer 2 S sums (fused)
    k_combine_reduce32<<<64, 256>>>(b1, S2, n);
    k_project<<<1, 128>>>(S2, W2, 32, 32);

    // Layer 2 output -> layer 3 S sums (fused)
    k_combine_reduce32<<<64, 256>>>(b2, S3, n);
    k_project<<<1, 64>>>(S3, W3, 32, 16);

    // Layer 3 + log_softmax
    k_final16<<<nb, 256>>>(b3, (float*)d_out, n);
}

// round 3
// speedup vs baseline: 3.2862x; 1.1600x over previous
#include <cuda_runtime.h>

static constexpr int NMAX = 8192;
static constexpr float CC = 5.0e-7f;   // 1/(2*1000^2)
static constexpr int NB = 148;
static constexpr int NT = 256;

// Scratch (device globals — no allocation allowed)
__device__ float  g_deg[NMAX];
__device__ float4 g_geom[NMAX];              // {px, py, r, -}
__device__ float4 g_U[NMAX];                 // {u0, u1, ux, uy}
__device__ __align__(16) float g_S[768];     // S1(4*64) | S2(4*32) | S3(4*32)
__device__ unsigned g_arr;                   // barrier arrive counter
__device__ unsigned g_gen;                   // barrier generation

__device__ __forceinline__ void redv4(float* p, float a, float b, float c, float d) {
    asm volatile("red.global.add.v4.f32 [%0], {%1,%2,%3,%4};"
                 :: "l"(p), "f"(a), "f"(b), "f"(c), "f"(d) : "memory");
}
__device__ __forceinline__ void redf(float* p, float v) {
    asm volatile("red.global.add.f32 [%0], %1;" :: "l"(p), "f"(v) : "memory");
}

// Software grid barrier (all NB blocks co-resident by construction).
__device__ __forceinline__ void gridbar() {
    __syncthreads();
    if (threadIdx.x == 0) {
        __threadfence();
        unsigned gen = *(volatile unsigned*)&g_gen;
        if (atomicAdd(&g_arr, 1u) == NB - 1u) {
            atomicExch(&g_arr, 0u);
            __threadfence();
            atomicAdd(&g_gen, 1u);                 // release
        } else {
            while (*(volatile unsigned*)&g_gen == gen) __nanosleep(32);
            __threadfence();                        // acquire
        }
    }
    __syncthreads();
}

// Block-redundant tiny GEMV: shT[q*Cout+c] = sum_k S[q*Cin+k] * W[k*Cout+c]
__device__ __forceinline__ void project_sh(const float* S, const float* __restrict__ W,
                                           int Cin, int Cout, float* shT) {
    int t = threadIdx.x;
    if (t < 4 * Cout) {
        int row = t / Cout, c = t - row * Cout;
        float acc = 0.f;
        for (int k = 0; k < Cin; k++) acc += S[row * Cin + k] * W[k * Cout + c];
        shT[row * Cout + c] = acc;
    }
    __syncthreads();
}

__device__ __forceinline__ float4 node_coeffs(float4 ge, float di, float4 u) {
    float px = ge.x, py = ge.y, r = ge.z;
    float di2 = di * di;
    float4 a;
    a.x = di * (u.x - CC * u.y) + di2 * (1.0f - CC * r);   // * T0
    a.y = -CC * (di * u.x + di2);                          // * T1
    a.z = 2.0f * CC * (di * u.z + di2 * px);               // * T2x
    a.w = 2.0f * CC * (di * u.w + di2 * py);               // * T2y
    return a;
}

// Shared-memory cross-row reduce of 4 accumulators, then red.v4 into Sout.
template <int G, int RPB>
__device__ __forceinline__ void block_reduce_emit(float4 s0, float4 s1, float4 s2, float4 s3,
                                                  float4* sm, float* Sout, int C) {
    int t = threadIdx.x, g = t % G, rl = t / G;
    sm[t * 4 + 0] = s0; sm[t * 4 + 1] = s1; sm[t * 4 + 2] = s2; sm[t * 4 + 3] = s3;
    __syncthreads();
    for (int s = RPB / 2; s >= 1; s >>= 1) {
        if (rl < s) {
            int o = (t + s * G) * 4;
#pragma unroll
            for (int q = 0; q < 4; q++) {
                float4 a = sm[t * 4 + q], b = sm[o + q];
                a.x += b.x; a.y += b.y; a.z += b.z; a.w += b.w;
                sm[t * 4 + q] = a;
            }
        }
        __syncthreads();
    }
    if (rl == 0) {
#pragma unroll
        for (int q = 0; q < 4; q++) {
            float4 v = sm[t * 4 + q];
            redv4(&Sout[q * C + 4 * g], v.x, v.y, v.z, v.w);
        }
    }
    __syncthreads();
}

__global__ void __launch_bounds__(NT)
k_fused(const float* __restrict__ x, const float* __restrict__ pos,
        const int* __restrict__ ei,
        const float* __restrict__ W1, const float* __restrict__ b1,
        const float* __restrict__ W2, const float* __restrict__ b2,
        const float* __restrict__ W3, const float* __restrict__ b3,
        float* __restrict__ out, int n, int E) {
    __shared__ float  shT[256];
    __shared__ float4 sm[NT * 4];
    int tid = threadIdx.x;
    int gt = blockIdx.x * NT + tid;
    int stride = NB * NT;

    // ---- Phase 1: init (deg=1 self-loop, U=0, S=0, geom) ----
    for (int i = gt; i < n; i += stride) {
        float px = pos[2 * i], py = pos[2 * i + 1];
        g_geom[i] = make_float4(px, py, px * px + py * py, 0.f);
        g_deg[i] = 1.0f;
        g_U[i] = make_float4(0.f, 0.f, 0.f, 0.f);
    }
    if (gt < 768) g_S[gt] = 0.0f;
    gridbar();

    // ---- Phase 2: degree count over edges  +  S1 reduction over x (C=64) ----
    for (int e = gt; e < E; e += stride) redf(&g_deg[ei[E + e]], 1.0f);
    {
        constexpr int C = 64, G = 16, RPB = NT / G;
        int g = tid % G, rl = tid / G;
        float4 s0 = {0,0,0,0}, s1 = {0,0,0,0}, s2 = {0,0,0,0}, s3 = {0,0,0,0};
        for (int i0 = blockIdx.x * RPB; i0 < n; i0 += NB * RPB) {
            int i = i0 + rl;
            if (i < n) {
                float4 v = *reinterpret_cast<const float4*>(&x[i * C + 4 * g]);
                float4 ge = g_geom[i];
                s0.x += v.x;        s0.y += v.y;        s0.z += v.z;        s0.w += v.w;
                s1.x += ge.z * v.x; s1.y += ge.z * v.y; s1.z += ge.z * v.z; s1.w += ge.z * v.w;
                s2.x += ge.x * v.x; s2.y += ge.x * v.y; s2.z += ge.x * v.z; s2.w += ge.x * v.w;
                s3.x += ge.y * v.x; s3.y += ge.y * v.y; s3.z += ge.y * v.z; s3.w += ge.y * v.w;
            }
        }
        block_reduce_emit<G, RPB>(s0, s1, s2, s3, sm, g_S, C);
    }
    gridbar();

    // ---- Phase 3: U scatter (dinv computed on the fly) ----
    for (int e = gt; e < E; e += stride) {
        int s = ei[e], d = ei[E + e];
        float4 ge = g_geom[s];
        float di = rsqrtf(g_deg[s]);
        redv4(reinterpret_cast<float*>(&g_U[d]), di, di * ge.z, di * ge.x, di * ge.y);
    }
    gridbar();

    // ---- Phase 4: T1 = S1@W1 (block-redundant), combine+relu, reduce -> S2 ----
    // ---- Phase 5: T2 = S2@W2, combine+relu, reduce -> S3 ----
    const float* Ws[2]   = {W1, W2};
    const float* bs[2]   = {b1, b2};
    for (int layer = 0; layer < 2; layer++) {
        project_sh(layer == 0 ? g_S : g_S + 256, Ws[layer], layer == 0 ? 64 : 32, 32, shT);
        constexpr int C = 32, G = 8, RPB = NT / G;
        int g = tid % G, rl = tid / G;
        float4 t0 = *reinterpret_cast<const float4*>(&shT[4 * g]);
        float4 t1 = *reinterpret_cast<const float4*>(&shT[C + 4 * g]);
        float4 t2 = *reinterpret_cast<const float4*>(&shT[2 * C + 4 * g]);
        float4 t3 = *reinterpret_cast<const float4*>(&shT[3 * C + 4 * g]);
        float4 bv = *reinterpret_cast<const float4*>(&bs[layer][4 * g]);
        float4 s0 = {0,0,0,0}, s1 = {0,0,0,0}, s2 = {0,0,0,0}, s3 = {0,0,0,0};
        for (int i0 = blockIdx.x * RPB; i0 < n; i0 += NB * RPB) {
            int i = i0 + rl;
            if (i < n) {
                float4 ge = g_geom[i];
                float di = rsqrtf(g_deg[i]);
                float4 a = node_coeffs(ge, di, g_U[i]);
                float4 v;
                v.x = fmaxf(a.x * t0.x + a.y * t1.x + a.z * t2.x + a.w * t3.x + bv.x, 0.f);
                v.y = fmaxf(a.x * t0.y + a.y * t1.y + a.z * t2.y + a.w * t3.y + bv.y, 0.f);
                v.z = fmaxf(a.x * t0.z + a.y * t1.z + a.z * t2.z + a.w * t3.z + bv.z, 0.f);
                v.w = fmaxf(a.x * t0.w + a.y * t1.w + a.z * t2.w + a.w * t3.w + bv.w, 0.f);
                s0.x += v.x;        s0.y += v.y;        s0.z += v.z;        s0.w += v.w;
                s1.x += ge.z * v.x; s1.y += ge.z * v.y; s1.z += ge.z * v.z; s1.w += ge.z * v.w;
                s2.x += ge.x * v.x; s2.y += ge.x * v.y; s2.z += ge.x * v.z; s2.w += ge.x * v.w;
                s3.x += ge.y * v.x; s3.y += ge.y * v.y; s3.z += ge.y * v.z; s3.w += ge.y * v.w;
            }
        }
        block_reduce_emit<G, RPB>(s0, s1, s2, s3, sm, layer == 0 ? g_S + 256 : g_S + 384, C);
        gridbar();
    }

    // ---- Phase 6: T3 = S3@W3, final combine + log_softmax ----
    project_sh(g_S + 384, W3, 32, 16, shT);
    for (int i = gt; i < n; i += stride) {
        float4 ge = g_geom[i];
        float di = rsqrtf(g_deg[i]);
        float4 a = node_coeffs(ge, di, g_U[i]);
        float v[16];
#pragma unroll
        for (int c = 0; c < 16; c++)
            v[c] = a.x * shT[c] + a.y * shT[16 + c] + a.z * shT[32 + c] + a.w * shT[48 + c]
                 + b3[c];
        float m = v[0];
#pragma unroll
        for (int c = 1; c < 16; c++) m = fmaxf(m, v[c]);
        float s = 0.f;
#pragma unroll
        for (int c = 0; c < 16; c++) s += __expf(v[c] - m);
        float l = m + __logf(s);
        float4* o = reinterpret_cast<float4*>(out + i * 16);
#pragma unroll
        for (int q = 0; q < 4; q++) {
            float4 w;
            w.x = v[4 * q] - l;     w.y = v[4 * q + 1] - l;
            w.z = v[4 * q + 2] - l; w.w = v[4 * q + 3] - l;
            o[q] = w;
        }
    }
}

extern "C" void kernel_launch(void* const* d_in, const int* in_sizes, int n_in,
                              void* d_out, int out_size) {
    const float* x   = (const float*)d_in[0];
    const float* pos = (const float*)d_in[1];
    const int*   ei  = (const int*)d_in[2];
    const float* W1  = (const float*)d_in[3];
    const float* b1  = (const float*)d_in[4];
    const float* W2  = (const float*)d_in[5];
    const float* b2  = (const float*)d_in[6];
    const float* W3  = (const float*)d_in[7];
    const float* b3  = (const float*)d_in[8];
    int n = in_sizes[1] / 2;   // pos is (N,2)
    int E = in_sizes[2] / 2;   // edge_index is (2,E)

    k_fused<<<NB, NT>>>(x, pos, ei, W1, b1, W2, b2, W3, b3, (float*)d_out, n, E);
}